// round 2
// baseline (speedup 1.0000x reference)
#include <cuda_runtime.h>
#include <cstdint>

typedef unsigned long long U64;
typedef unsigned int U32;

#define NLINES (512*512)          // 262144 lines of 48 voxels
#define NVOX   (512*512*48)       // 12582912
#define NGRP   (NVOX/4)           // 3145728 groups of 4 voxels
#define MCL    4096
#define ACC_GRID 148
#define ACC_BIAS (ACC_GRID << 20) // flush bias: every block flushes every bin once

// -------- scratch (static device globals; no allocation) --------
__device__ U64  g_m1[NLINES];
__device__ U64  g_m2[NLINES];
__device__ U64  g_m3[NLINES];
__device__ U64  g_pA[MCL];         // lo32: s0+bias, hi32: s1+bias
__device__ U64  g_pB[MCL];         // lo32: s2+bias, hi32: count
__device__ float g_cent[MCL*3];
__device__ U64   g_keys[MCL];
__device__ int   g_order[MCL];
__device__ float g_bs[MCL*4];      // sorted boxes (as float4)
__device__ U64   g_keep0[64];      // keep0 bitmask in sorted rank space
__device__ U64   g_supp[MCL*64];   // suppression bitmatrix (sorted space)

// -------- 0: zero accumulators (graph replays must reset state) --------
__global__ void k_zero() {
    int t = blockIdx.x * blockDim.x + threadIdx.x;
    if (t < MCL) { g_pA[t] = 0ULL; g_pB[t] = 0ULL; }
}

// -------- 1: binarize + erode along k (width-9 min) via bit tricks --------
__global__ void k_erode_k(const float* __restrict__ pm) {
    int line = blockIdx.x * blockDim.x + threadIdx.x;
    if (line >= NLINES) return;
    const float4* p = reinterpret_cast<const float4*>(pm) + (size_t)line * 12;
    U64 b = 0ULL;
#pragma unroll
    for (int i = 0; i < 12; i++) {
        float4 v = __ldg(p + i);
        U64 nib = (U64)((v.x > 0.5f) | ((v.y > 0.5f) << 1) |
                        ((v.z > 0.5f) << 2) | ((v.w > 0.5f) << 3));
        b |= nib << (i * 4);
    }
    U64 r = b;
#pragma unroll
    for (int s = 1; s <= 4; s++) r &= (b >> s) & (b << s);
    g_m1[line] = r;
}

// -------- 2: erode along j (stride 1 in line index) --------
__global__ void k_erode_j() {
    int idx = blockIdx.x * blockDim.x + threadIdx.x;
    if (idx >= NLINES) return;
    int j = idx & 511;
    U64 r = g_m1[idx];
#pragma unroll
    for (int d = 1; d <= 4; d++) {
        U64 a = (j - d >= 0)  ? __ldg(&g_m1[idx - d]) : 0ULL;
        U64 c = (j + d < 512) ? __ldg(&g_m1[idx + d]) : 0ULL;
        r &= a & c;
    }
    g_m2[idx] = r;
}

// -------- 3: erode along i (stride 512 in line index) --------
__global__ void k_erode_i() {
    int idx = blockIdx.x * blockDim.x + threadIdx.x;
    if (idx >= NLINES) return;
    int i = idx >> 9;
    U64 r = g_m2[idx];
#pragma unroll
    for (int d = 1; d <= 4; d++) {
        U64 a = (i - d >= 0)  ? __ldg(&g_m2[idx - d * 512]) : 0ULL;
        U64 c = (i + d < 512) ? __ldg(&g_m2[idx + d * 512]) : 0ULL;
        r &= a & c;
    }
    g_m3[idx] = r;
}

// -------- 4: hash + segment accumulate --------
// One packed 64-bit shared atomic per valid voxel:
//   bits [0:18)  s0 partial (+1024 bias per add)
//   bits [18:36) s1 partial
//   bits [36:54) s2 partial
//   bits [54:64) count
// Per-block-per-bin adds ~= 20 << 128 (field overflow cap) with this input.
__global__ void __launch_bounds__(1024, 1) k_accum(const float* __restrict__ emb) {
    __shared__ U64 s_acc[MCL];
    int tid = threadIdx.x;
    for (int i = tid; i < MCL; i += 1024) s_acc[i] = 0ULL;
    __syncthreads();

    const float4* p0 = reinterpret_cast<const float4*>(emb);
    const float4* p1 = p0 + NGRP;
    const float4* p2 = p0 + 2 * NGRP;

    const unsigned stride = gridDim.x * blockDim.x;
    for (unsigned g = blockIdx.x * blockDim.x + tid; g < NGRP; g += stride) {
        unsigned line = g / 12u;
        unsigned kb = (g - line * 12u) * 4u;
        U32 mb = (U32)((__ldg(&g_m3[line]) >> kb) & 0xFULL);
        if (!mb) continue;
        float4 ex = __ldg(p0 + g);
        float4 ey = __ldg(p1 + g);
        float4 ez = __ldg(p2 + g);
        float X[4] = {ex.x, ex.y, ex.z, ex.w};
        float Y[4] = {ey.x, ey.y, ey.z, ey.w};
        float Z[4] = {ez.x, ez.y, ez.z, ez.w};
#pragma unroll
        for (int c = 0; c < 4; c++) {
            if (!((mb >> c) & 1u)) continue;
            float a = X[c], b = Y[c], cc = Z[c];
            if (!(a > -2.0f || b > -2.0f || cc > -2.0f)) continue;
            float c0 = rintf(a * 25.0f);
            float c1 = rintf(b * 25.0f);
            float c2 = rintf(cc * 25.0f);
            U32 q0 = (U32)fminf(fmaxf(c0 + 128.0f, 0.0f), 255.0f);
            U32 q1 = (U32)fminf(fmaxf(c1 + 128.0f, 0.0f), 255.0f);
            U32 q2 = (U32)fminf(fmaxf(c2 + 128.0f, 0.0f), 255.0f);
            U32 seg = (q0 * 73856093u ^ q1 * 19349663u ^ q2 * 83492791u) & 4095u;
            int iv0 = (int)c0, iv1 = (int)c1, iv2 = (int)c2;
            U64 add = (1ULL << 54)
                    | (U64)(U32)(iv0 + 1024)
                    | ((U64)(U32)(iv1 + 1024) << 18)
                    | ((U64)(U32)(iv2 + 1024) << 36);
            atomicAdd(&s_acc[seg], add);
        }
    }
    __syncthreads();

    // flush: every block flushes every bin exactly once (bias bookkeeping)
    for (int b = tid; b < MCL; b += 1024) {
        U64 v = s_acc[b];
        U32 cnt = (U32)(v >> 54);
        int bias = (int)cnt * 1024;
        int s0 = (int)(v & 0x3FFFFULL) - bias;
        int s1 = (int)((v >> 18) & 0x3FFFFULL) - bias;
        int s2 = (int)((v >> 36) & 0x3FFFFULL) - bias;
        U64 A = (U64)(U32)(s0 + (1 << 20)) | ((U64)(U32)(s1 + (1 << 20)) << 32);
        U64 B = (U64)(U32)(s2 + (1 << 20)) | ((U64)cnt << 32);
        atomicAdd(&g_pA[b], A);
        atomicAdd(&g_pB[b], B);
    }
}

// -------- 5: centroids + sort keys --------
__global__ void k_finalize(float* __restrict__ out) {
    int b = blockIdx.x * blockDim.x + threadIdx.x;
    if (b >= MCL) return;
    U64 A = g_pA[b], B = g_pB[b];
    U32 cnt = (U32)(B >> 32);
    float s0 = (float)((int)(U32)A - ACC_BIAS);
    float s1 = (float)((int)(U32)(A >> 32) - ACC_BIAS);
    float s2 = (float)((int)(U32)B - ACC_BIAS);
    float d = fmaxf((float)cnt, 1.0f);
    float c0 = s0 / d, c1 = s1 / d, c2 = s2 / d;
    out[b*3+0] = c0; out[b*3+1] = c1; out[b*3+2] = c2;
    g_cent[b*3+0] = c0; g_cent[b*3+1] = c1; g_cent[b*3+2] = c2;
    // key: (count+1 if is_cluster else 0) desc, then idx asc (via 4095-idx)
    U64 c1k = (cnt >= 10u) ? (U64)(cnt + 1u) : 0ULL;
    g_keys[b] = (c1k << 12) | (U64)(4095 - b);
}

// -------- 6: bitonic sort (descending) + sorted boxes/keep0 --------
__global__ void k_sort() {
    __shared__ U64 sk[MCL];
    int tid = threadIdx.x;
    for (int i = tid; i < MCL; i += blockDim.x) sk[i] = g_keys[i];
    if (tid < 64) g_keep0[tid] = 0ULL;
    __syncthreads();
    for (int k = 2; k <= MCL; k <<= 1) {
        for (int j = k >> 1; j > 0; j >>= 1) {
            for (int i = tid; i < MCL; i += blockDim.x) {
                int ixj = i ^ j;
                if (ixj > i) {
                    bool dir = ((i & k) == 0);
                    U64 a = sk[i], b2 = sk[ixj];
                    if ((a < b2) == dir) { sk[i] = b2; sk[ixj] = a; }
                }
            }
            __syncthreads();
        }
    }
    for (int r = tid; r < MCL; r += blockDim.x) {
        U64 key = sk[r];
        int idx = 4095 - (int)(key & 4095ULL);
        g_order[r] = idx;
        float cx = g_cent[idx*3+0];
        float cy = g_cent[idx*3+1];
        g_bs[r*4+0] = cx - 22.5f;
        g_bs[r*4+1] = cy - 22.5f;
        g_bs[r*4+2] = cx + 22.5f;
        g_bs[r*4+3] = cy + 22.5f;
        if ((key >> 12) >= 11ULL)   // count >= 10
            atomicOr(&g_keep0[r >> 6], 1ULL << (r & 63));
    }
}

// -------- 7: suppression bitmatrix, tiled (cols staged in shared) --------
__global__ void k_supp() {
    int rb = blockIdx.y, cb = blockIdx.x;
    int t = threadIdx.x;                 // 0..63
    int r = rb * 64 + t;
    if (cb < rb) { g_supp[r*64 + cb] = 0ULL; return; } // uniform branch
    __shared__ float4 sb[64];
    const float4* boxes = reinterpret_cast<const float4*>(g_bs);
    sb[t] = boxes[cb * 64 + t];
    __syncthreads();
    float4 a = boxes[r];
    float a1 = (a.z - a.x) * (a.w - a.y);
    U64 bits = 0ULL;
#pragma unroll 8
    for (int jj = 0; jj < 64; jj++) {
        int j = cb * 64 + jj;
        if (j <= r) continue;
        float4 bb = sb[jj];
        float x1 = fmaxf(a.x, bb.x), y1 = fmaxf(a.y, bb.y);
        float x2 = fminf(a.z, bb.z), y2 = fminf(a.w, bb.w);
        float inter = fmaxf(x2 - x1, 0.0f) * fmaxf(y2 - y1, 0.0f);
        float a2 = (bb.z - bb.x) * (bb.w - bb.y);
        float iou = inter / fmaxf(a1 + a2 - inter, 1e-9f);
        if (iou > 0.5f) bits |= (1ULL << jj);
    }
    g_supp[r*64 + cb] = bits;
}

// -------- 8: single-warp greedy NMS + scatter keep --------
__global__ void k_greedy(float* __restrict__ out, int write_keep) {
    __shared__ U64 kw[64];
    int l = threadIdx.x;               // lane l owns rank words 2l, 2l+1
    U64 k0a = g_keep0[2*l], k0b = g_keep0[2*l+1];
    U64 rem0 = 0ULL, rem1 = 0ULL, done0 = 0ULL, done1 = 0ULL;
    while (true) {
        U64 ca = k0a & ~rem0 & ~done0;
        U64 cb = k0b & ~rem1 & ~done1;
        int best = 0x7fffffff;
        if (ca)      best = (__ffsll((long long)ca) - 1) + l * 128;
        else if (cb) best = (__ffsll((long long)cb) - 1) + l * 128 + 64;
#pragma unroll
        for (int o = 16; o; o >>= 1)
            best = min(best, __shfl_xor_sync(0xffffffffu, best, o));
        if (best == 0x7fffffff) break;
        if ((best >> 7) == l) {
            if (((best >> 6) & 1) == 0) done0 |= 1ULL << (best & 63);
            else                        done1 |= 1ULL << (best & 63);
        }
        rem0 |= __ldg(&g_supp[best*64 + 2*l]);
        rem1 |= __ldg(&g_supp[best*64 + 2*l + 1]);
    }
    kw[2*l]     = k0a & ~rem0;
    kw[2*l + 1] = k0b & ~rem1;
    __syncwarp();
    if (write_keep) {
        for (int r = l; r < MCL; r += 32) {
            U64 wv = kw[r >> 6];
            out[12288 + g_order[r]] = ((wv >> (r & 63)) & 1ULL) ? 1.0f : 0.0f;
        }
    }
}

extern "C" void kernel_launch(void* const* d_in, const int* in_sizes, int n_in,
                              void* d_out, int out_size) {
    // embedding has 3*NVOX elements, probability_map has NVOX
    const float* emb = (const float*)d_in[0];
    const float* pm  = (const float*)d_in[1];
    if (n_in >= 2 && in_sizes[0] == NVOX && in_sizes[1] == 3*NVOX) {
        emb = (const float*)d_in[1];
        pm  = (const float*)d_in[0];
    }
    float* out = (float*)d_out;

    k_zero   <<<16, 256>>>();
    k_erode_k<<<NLINES/256, 256>>>(pm);
    k_erode_j<<<NLINES/256, 256>>>();
    k_erode_i<<<NLINES/256, 256>>>();
    k_accum  <<<ACC_GRID, 1024>>>(emb);
    k_finalize<<<16, 256>>>(out);
    k_sort   <<<1, 1024>>>();
    k_supp   <<<dim3(64, 64), 64>>>();
    k_greedy <<<1, 32>>>(out, (out_size >= 12288 + MCL) ? 1 : 0);
}

// round 3
// speedup vs baseline: 2.0757x; 2.0757x over previous
#include <cuda_runtime.h>
#include <cstdint>

typedef unsigned long long U64;
typedef unsigned int U32;

#define NLINES (512*512)          // 262144 lines of 48 voxels
#define NVOX   (512*512*48)       // 12582912
#define NGRP   (NVOX/4)           // 3145728 groups of 4 voxels
#define MCL    4096
#define ACC_GRID 148
#define ACC_BIAS (ACC_GRID << 20) // per-block flush bias

// -------- scratch (static device globals; no allocation) --------
__device__ U64  g_m1[NLINES];      // after k-erosion
__device__ U64  g_m3[NLINES];      // after j+i erosion
__device__ U64  g_pA[MCL];         // lo32: s0+bias, hi32: s1+bias
__device__ U64  g_pB[MCL];         // lo32: s2+bias, hi32: count
__device__ U64  g_keys[MCL];       // (count+1 or 0)<<12 | (4095-idx)
__device__ float g_bs[MCL*4];      // boxes in ORIGINAL index space (float4)

// -------- 1: binarize + erode along k (width-9 min) + zero accumulators ----
__global__ void k_erode_k(const float* __restrict__ pm) {
    int line = blockIdx.x * blockDim.x + threadIdx.x;
    if (line < MCL) { g_pA[line] = 0ULL; g_pB[line] = 0ULL; }
    if (line >= NLINES) return;
    const float4* p = reinterpret_cast<const float4*>(pm) + (size_t)line * 12;
    U64 b = 0ULL;
#pragma unroll
    for (int i = 0; i < 12; i++) {
        float4 v = __ldg(p + i);
        U64 nib = (U64)((v.x > 0.5f) | ((v.y > 0.5f) << 1) |
                        ((v.z > 0.5f) << 2) | ((v.w > 0.5f) << 3));
        b |= nib << (i * 4);
    }
    U64 r = b;
#pragma unroll
    for (int s = 1; s <= 4; s++) r &= (b >> s) & (b << s);
    g_m1[line] = r;
}

// -------- 2: fused erode along j then i (32x32 line tiles, 4-halo) --------
__global__ void k_erode_ji() {
    __shared__ U64 sA[40][41];   // rows i0-4..i0+35, cols j0-4..j0+35
    __shared__ U64 sB[40][33];   // j-eroded, rows i0-4..i0+35, cols j0..j0+31
    int i0 = blockIdx.y * 32, j0 = blockIdx.x * 32;
    int t = threadIdx.x;         // 256 threads

    for (int p = t; p < 40 * 40; p += 256) {
        int r = p / 40, c = p - r * 40;
        int i = i0 + r - 4, j = j0 + c - 4;
        U64 v = 0ULL;
        if ((unsigned)i < 512u && (unsigned)j < 512u) v = g_m1[i * 512 + j];
        sA[r][c] = v;
    }
    __syncthreads();
    for (int p = t; p < 40 * 32; p += 256) {
        int r = p >> 5, c = p & 31;
        U64 v = sA[r][c];
#pragma unroll
        for (int d = 1; d <= 8; d++) v &= sA[r][c + d];
        sB[r][c] = v;
    }
    __syncthreads();
    for (int p = t; p < 32 * 32; p += 256) {
        int r = p >> 5, c = p & 31;
        U64 v = sB[r][c];
#pragma unroll
        for (int d = 1; d <= 8; d++) v &= sB[r + d][c];
        g_m3[(i0 + r) * 512 + (j0 + c)] = v;
    }
}

// -------- 3: hash + segment accumulate --------
// One packed 64-bit shared atomic per valid voxel:
//   [0:18) s0+1024/add, [18:36) s1, [36:54) s2, [54:64) count
__global__ void __launch_bounds__(1024, 1) k_accum(const float* __restrict__ emb) {
    __shared__ U64 s_acc[MCL];
    int tid = threadIdx.x;
    for (int i = tid; i < MCL; i += 1024) s_acc[i] = 0ULL;
    __syncthreads();

    const float4* p0 = reinterpret_cast<const float4*>(emb);
    const float4* p1 = p0 + NGRP;
    const float4* p2 = p0 + 2 * NGRP;

    const unsigned stride = gridDim.x * blockDim.x;
    for (unsigned g = blockIdx.x * blockDim.x + tid; g < NGRP; g += stride) {
        unsigned line = g / 12u;
        unsigned kb = (g - line * 12u) * 4u;
        U32 mb = (U32)((__ldg(&g_m3[line]) >> kb) & 0xFULL);
        if (!mb) continue;
        float4 ex = __ldg(p0 + g);
        float4 ey = __ldg(p1 + g);
        float4 ez = __ldg(p2 + g);
        float X[4] = {ex.x, ex.y, ex.z, ex.w};
        float Y[4] = {ey.x, ey.y, ey.z, ey.w};
        float Z[4] = {ez.x, ez.y, ez.z, ez.w};
#pragma unroll
        for (int c = 0; c < 4; c++) {
            if (!((mb >> c) & 1u)) continue;
            float a = X[c], b = Y[c], cc = Z[c];
            if (!(a > -2.0f || b > -2.0f || cc > -2.0f)) continue;
            float c0 = rintf(a * 25.0f);
            float c1 = rintf(b * 25.0f);
            float c2 = rintf(cc * 25.0f);
            U32 q0 = (U32)fminf(fmaxf(c0 + 128.0f, 0.0f), 255.0f);
            U32 q1 = (U32)fminf(fmaxf(c1 + 128.0f, 0.0f), 255.0f);
            U32 q2 = (U32)fminf(fmaxf(c2 + 128.0f, 0.0f), 255.0f);
            U32 seg = (q0 * 73856093u ^ q1 * 19349663u ^ q2 * 83492791u) & 4095u;
            U64 add = (1ULL << 54)
                    | (U64)(U32)((int)c0 + 1024)
                    | ((U64)(U32)((int)c1 + 1024) << 18)
                    | ((U64)(U32)((int)c2 + 1024) << 36);
            atomicAdd(&s_acc[seg], add);
        }
    }
    __syncthreads();

    for (int b = tid; b < MCL; b += 1024) {
        U64 v = s_acc[b];
        U32 cnt = (U32)(v >> 54);
        int bias = (int)cnt * 1024;
        int s0 = (int)(v & 0x3FFFFULL) - bias;
        int s1 = (int)((v >> 18) & 0x3FFFFULL) - bias;
        int s2 = (int)((v >> 36) & 0x3FFFFULL) - bias;
        U64 A = (U64)(U32)(s0 + (1 << 20)) | ((U64)(U32)(s1 + (1 << 20)) << 32);
        U64 B = (U64)(U32)(s2 + (1 << 20)) | ((U64)cnt << 32);
        atomicAdd(&g_pA[b], A);
        atomicAdd(&g_pB[b], B);
    }
}

// -------- 4: centroids + keys + boxes --------
__global__ void k_finalize(float* __restrict__ out) {
    int b = blockIdx.x * blockDim.x + threadIdx.x;
    if (b >= MCL) return;
    U64 A = g_pA[b], B = g_pB[b];
    U32 cnt = (U32)(B >> 32);
    float s0 = (float)((int)(U32)A - ACC_BIAS);
    float s1 = (float)((int)(U32)(A >> 32) - ACC_BIAS);
    float s2 = (float)((int)(U32)B - ACC_BIAS);
    float d = fmaxf((float)cnt, 1.0f);
    float c0 = s0 / d, c1 = s1 / d, c2 = s2 / d;
    out[b*3+0] = c0; out[b*3+1] = c1; out[b*3+2] = c2;
    g_bs[b*4+0] = c0 - 22.5f;
    g_bs[b*4+1] = c1 - 22.5f;
    g_bs[b*4+2] = c0 + 22.5f;
    g_bs[b*4+3] = c1 + 22.5f;
    U64 c1k = (cnt >= 10u) ? (U64)(cnt + 1u) : 0ULL;
    g_keys[b] = (c1k << 12) | (U64)(4095 - b);
}

// -------- 5: exact greedy NMS via max-key selection (1 block) --------
// key order == reference argsort(-scores) (stable, idx-asc ties).
// Each pivot = alive cluster with max key; suppress j with key_j < key_pivot
// and IoU > 0.5. Iterations == #survivors (tiny for overlapping boxes).
__global__ void k_nms(float* __restrict__ out, int write_keep) {
    __shared__ U64 sk[MCL];       // keys
    __shared__ U64 swarp[8];
    __shared__ U64 sbest;
    int t = threadIdx.x;          // 256 threads; thread t owns idx = t + 256*s
    for (int i = t; i < MCL; i += 256) sk[i] = g_keys[i];
    U32 rm = 0, dn = 0;           // removed / pivot-done bits (s = idx>>8)
    const float4* boxes = reinterpret_cast<const float4*>(g_bs);
    __syncthreads();

    const U64 CLUS = (U64)11 << 12;   // key >= this  <=>  count >= 10
    while (true) {
        U64 m = 0ULL;
#pragma unroll
        for (int s = 0; s < 16; s++) {
            if ((rm >> s) & 1u) continue;
            if ((dn >> s) & 1u) continue;
            U64 k = sk[t + 256 * s];
            if (k >= CLUS && k > m) m = k;
        }
#pragma unroll
        for (int o = 16; o; o >>= 1) {
            U64 other = __shfl_xor_sync(0xffffffffu, m, o);
            if (other > m) m = other;
        }
        if ((t & 31) == 0) swarp[t >> 5] = m;
        __syncthreads();
        if (t == 0) {
            U64 mm = swarp[0];
#pragma unroll
            for (int w = 1; w < 8; w++) if (swarp[w] > mm) mm = swarp[w];
            sbest = mm;
        }
        __syncthreads();
        U64 best = sbest;
        __syncthreads();
        if (best == 0ULL) break;
        int pivot = 4095 - (int)(best & 4095ULL);
        if ((pivot & 255) == t) dn |= 1u << (pivot >> 8);
        float4 pb = boxes[pivot];
        float pa = (pb.z - pb.x) * (pb.w - pb.y);
#pragma unroll
        for (int s = 0; s < 16; s++) {
            if ((rm >> s) & 1u) continue;
            int idx = t + 256 * s;
            if (sk[idx] >= best) continue;   // only lower-ranked suppressed
            float4 bb = boxes[idx];
            float x1 = fmaxf(pb.x, bb.x), y1 = fmaxf(pb.y, bb.y);
            float x2 = fminf(pb.z, bb.z), y2 = fminf(pb.w, bb.w);
            float inter = fmaxf(x2 - x1, 0.0f) * fmaxf(y2 - y1, 0.0f);
            float a2 = (bb.z - bb.x) * (bb.w - bb.y);
            float iou = inter / fmaxf(pa + a2 - inter, 1e-9f);
            if (iou > 0.5f) rm |= 1u << s;
        }
    }
    if (write_keep) {
#pragma unroll
        for (int s = 0; s < 16; s++) {
            int idx = t + 256 * s;
            bool keep = (sk[idx] >= CLUS) && !((rm >> s) & 1u);
            out[12288 + idx] = keep ? 1.0f : 0.0f;
        }
    }
}

extern "C" void kernel_launch(void* const* d_in, const int* in_sizes, int n_in,
                              void* d_out, int out_size) {
    const float* emb = (const float*)d_in[0];
    const float* pm  = (const float*)d_in[1];
    if (n_in >= 2 && in_sizes[0] == NVOX && in_sizes[1] == 3*NVOX) {
        emb = (const float*)d_in[1];
        pm  = (const float*)d_in[0];
    }
    float* out = (float*)d_out;

    k_erode_k <<<NLINES/256, 256>>>(pm);
    k_erode_ji<<<dim3(16, 16), 256>>>();
    k_accum   <<<ACC_GRID, 1024>>>(emb);
    k_finalize<<<16, 256>>>(out);
    k_nms     <<<1, 256>>>(out, (out_size >= 12288 + MCL) ? 1 : 0);
}